// round 10
// baseline (speedup 1.0000x reference)
#include <cuda_runtime.h>
#include <cuda_bf16.h>
#include <cstdint>

// Problem constants
#define CDIM   256
#define HW     1024             // 32*32
#define KCODE  1024
#define MTILE  64               // z rows per block
#define KCHUNK 128              // codes per chunk
#define NCHUNK (KCODE / KCHUNK) // 8
#define NTHREADS 256

// dynamic smem (floats):
//   zt : [257 c][64 m] permuted z tile (1 pad row for prefetch overrun)
//   et : [257 c][132]  c-major e tile (stride 132, 1 pad row)
// epilogue overlays eg[64*257] on the base of the region.
#define ZT_FLOATS   ((CDIM + 1) * MTILE)   // 16448
#define ET_STRIDE   132
#define ET_FLOATS   ((CDIM + 1) * ET_STRIDE)   // 33924
#define SMEM_FLOATS (ZT_FLOATS + ET_FLOATS)
#define SMEM_BYTES  (SMEM_FLOATS * 4)          // 201488 B

__device__ float g_esq[KCODE];

// packed f32x2 FMA: each lane bitwise-identical to fma.rn.f32
__device__ __forceinline__ void ffma2(unsigned long long& acc,
                                      unsigned long long a,
                                      unsigned long long b) {
    asm("fma.rn.f32x2 %0, %1, %2, %0;" : "+l"(acc) : "l"(a), "l"(b));
}
__device__ __forceinline__ unsigned long long splat2(float e) {
    unsigned long long r;
    asm("mov.b64 %0, {%1, %1};" : "=l"(r) : "f"(e));
    return r;
}
__device__ __forceinline__ void unpack2(unsigned long long v, float& lo, float& hi) {
    asm("mov.b64 {%0, %1}, %2;" : "=f"(lo), "=f"(hi) : "l"(v));
}

// ---------------------------------------------------------------------------
// Kernel 0: e_sq[k] = sum_c emb[k][c]^2, SEQUENTIAL fp32 mul-then-add.
// ---------------------------------------------------------------------------
__global__ void vq_esq_kernel(const float* __restrict__ emb,
                              float* __restrict__ out, int out_size, int nz) {
    int k = blockIdx.x * blockDim.x + threadIdx.x;
    if (k < KCODE) {
        const float* e = emb + (size_t)k * CDIM;
        float s = 0.f;
        #pragma unroll 8
        for (int c = 0; c < CDIM; ++c) {
            float v = e[c];
            s = __fadd_rn(s, __fmul_rn(v, v));
        }
        g_esq[k] = s;
    }
    if (blockIdx.x == 0 && threadIdx.x == 0 && out_size > nz)
        out[nz] = 0.0f;
}

// ---------------------------------------------------------------------------
// Main kernel: 256 threads, 1 CTA/SM (8 warps, 2/SMSP). z tile resident;
// 8 k-chunks of 128 codes in c-major et (one LDS.128 per thread per c gets
// its 4 codes). Per-thread tile 8 rows x 4 codes; 1-deep register prefetch.
//   thread map: tm = tid&7 (rows tm*8..+7), tk = tid>>3 (codes tk*4..+3)
//   zt quad q=m>>2 at word (q>>1)*4 + (q&1)*32 (+ m&3)
// ---------------------------------------------------------------------------
__global__ __launch_bounds__(NTHREADS, 1)
void vq_main_kernel(const float* __restrict__ z,
                    const float* __restrict__ emb,
                    float* __restrict__ out, int out_size, int nz) {
    extern __shared__ float smem[];
    float* zt = smem;                  // [c*64 + permuted m]
    float* et = smem + ZT_FLOATS;      // [c*132 + k]
    float* eg = smem;                  // epilogue overlay: [m*257 + c]
    __shared__ unsigned long long red[MTILE];
    __shared__ float zsq_sm[MTILE];
    __shared__ float wsum[8];

    const int tid = threadIdx.x;
    const int tm  = tid & 7;           // 8 row groups of 8
    const int tk  = tid >> 3;          // 32 code groups of 4 (per chunk)
    const int b   = blockIdx.x >> 4;
    const int hw0 = (blockIdx.x & 15) * MTILE;

    const float* zbase = z + (size_t)b * CDIM * HW + hw0;

    if (tid < MTILE) red[tid] = 0xFFFFFFFFFFFFFFFFull;

    // ---- fill zt ONCE: quad m4 -> word (m4>>1)*4 + (m4&1)*32 ---------------
    #pragma unroll
    for (int it = 0; it < 16; ++it) {
        int lin = it * NTHREADS + tid;     // 4096 float4
        int c   = lin >> 4;
        int m4  = lin & 15;
        float4 v = *(const float4*)(zbase + (size_t)c * HW + m4 * 4);
        int pw = (m4 >> 1) * 4 + (m4 & 1) * 32;
        *(float4*)(zt + c * 64 + pw) = v;
    }
    __syncthreads();

    // ---- z_sq per row: SEQUENTIAL fp32, unfused mul+add (exact order) ------
    if (tid < MTILE) {
        int m  = tid;
        int q  = m >> 2;
        int pw = (q >> 1) * 4 + (q & 1) * 32 + (m & 3);
        float s = 0.f;
        #pragma unroll 8
        for (int c = 0; c < CDIM; ++c) {
            float v = zt[c * 64 + pw];
            s = __fadd_rn(s, __fmul_rn(v, v));
        }
        zsq_sm[m] = s;
    }

    float best[8];
    int   bidx[8];
    #pragma unroll
    for (int i = 0; i < 8; ++i) { best[i] = 3.4e38f; bidx[i] = 0; }

    const float* zc   = zt + tm * 4;
    const float* ecol = et + tk * 4;

    for (int chunk = 0; chunk < NCHUNK; ++chunk) {
        __syncthreads();   // prior compute read et; safe to overwrite

        // ---- fill et (transpose to c-major): warp = 8 k x 4 c4-groups ------
        const float* ebase = emb + (size_t)chunk * KCHUNK * CDIM;
        #pragma unroll 4
        for (int it = 0; it < 32; ++it) {
            int lin4 = it * NTHREADS + tid;   // 0..8191
            int klow = lin4 & 7;
            int cg   = (lin4 >> 3) & 3;
            int kh   = (lin4 >> 5) & 15;
            int ch   = (lin4 >> 9) & 15;
            int k    = kh * 8 + klow;
            int c4   = (ch * 4 + cg) * 4;     // float index, multiple of 4
            float4 v = *(const float4*)(ebase + k * CDIM + c4);
            float* d = et + k;
            d[(c4 + 0) * ET_STRIDE] = v.x;
            d[(c4 + 1) * ET_STRIDE] = v.y;
            d[(c4 + 2) * ET_STRIDE] = v.z;
            d[(c4 + 3) * ET_STRIDE] = v.w;
        }
        __syncthreads();

        // ---- compute: 256 c iters; prefetched 2 z-LDS.128 + 1 e-LDS.128 ----
        unsigned long long acc[4][4];  // [row-pair p][code j]
        #pragma unroll
        for (int p = 0; p < 4; ++p)
            #pragma unroll
            for (int j = 0; j < 4; ++j) acc[p][j] = 0ull;

        ulonglong2 pz0 = *(const ulonglong2*)(zc);
        ulonglong2 pz1 = *(const ulonglong2*)(zc + 32);
        float4     pe  = *(const float4*)(ecol);

        #pragma unroll 4
        for (int c = 0; c < CDIM; ++c) {
            ulonglong2 z0 = pz0, z1 = pz1;
            float4 ev = pe;
            // prefetch next c (c=255 reads pad row; never consumed)
            pz0 = *(const ulonglong2*)(zc + (c + 1) * 64);
            pz1 = *(const ulonglong2*)(zc + (c + 1) * 64 + 32);
            pe  = *(const float4*)(ecol + (c + 1) * ET_STRIDE);

            unsigned long long e0 = splat2(ev.x);
            unsigned long long e1 = splat2(ev.y);
            unsigned long long e2 = splat2(ev.z);
            unsigned long long e3 = splat2(ev.w);
            ffma2(acc[0][0], z0.x, e0); ffma2(acc[0][1], z0.x, e1);
            ffma2(acc[0][2], z0.x, e2); ffma2(acc[0][3], z0.x, e3);
            ffma2(acc[1][0], z0.y, e0); ffma2(acc[1][1], z0.y, e1);
            ffma2(acc[1][2], z0.y, e2); ffma2(acc[1][3], z0.y, e3);
            ffma2(acc[2][0], z1.x, e0); ffma2(acc[2][1], z1.x, e1);
            ffma2(acc[2][2], z1.x, e2); ffma2(acc[2][3], z1.x, e3);
            ffma2(acc[3][0], z1.y, e0); ffma2(acc[3][1], z1.y, e1);
            ffma2(acc[3][2], z1.y, e2); ffma2(acc[3][3], z1.y, e3);
        }

        // ---- fold chunk into per-thread running argmin ----------------------
        // d = fl( fl(z_sq + e_sq) - fl(2*e_z) ); ascending chunk/j + strict <
        {
            float esql[4];
            #pragma unroll
            for (int j = 0; j < 4; ++j)
                esql[j] = __ldg(&g_esq[chunk * KCHUNK + tk * 4 + j]);

            #pragma unroll
            for (int p = 0; p < 4; ++p) {
                #pragma unroll
                for (int bb = 0; bb < 2; ++bb) {
                    int i = 2 * p + bb;                 // local row 0..7
                    float zsq = zsq_sm[tm * 8 + i];
                    #pragma unroll
                    for (int j = 0; j < 4; ++j) {
                        float lo, hi; unpack2(acc[p][j], lo, hi);
                        float ez = bb ? hi : lo;
                        float u = __fadd_rn(zsq, esql[j]);
                        float d = __fsub_rn(u, __fmul_rn(2.0f, ez));
                        if (d < best[i]) {
                            best[i] = d;
                            bidx[i] = chunk * KCHUNK + tk * 4 + j;
                        }
                    }
                }
            }
        }
    }

    // ---- single packed-key atomicMin per owned row ---------------------------
    #pragma unroll
    for (int i = 0; i < 8; ++i) {
        int m = tm * 8 + i;
        unsigned u = __float_as_uint(best[i]);
        u = (u & 0x80000000u) ? ~u : (u | 0x80000000u);
        unsigned long long key =
            ((unsigned long long)u << 32) | (unsigned)bidx[i];
        atomicMin(&red[m], key);
    }
    __syncthreads();

    // ---- gather: eg[m*257 + c] = emb[idx[m]][c] (coalesced rows) -------------
    #pragma unroll 4
    for (int m = 0; m < MTILE; ++m) {
        int kb = (int)(red[m] & 0xFFFFFFFFull);
        eg[m * 257 + tid] = emb[(size_t)kb * CDIM + tid];
    }
    __syncthreads();

    // ---- write z_q (float4) + loss partial (z re-read from gmem) -------------
    float lsum = 0.f;
    float* obase = out + (size_t)b * CDIM * HW + hw0;
    #pragma unroll 4
    for (int it = 0; it < 16; ++it) {
        int lin = it * NTHREADS + tid;       // 4096 float4
        int c   = lin >> 4;
        int m4  = lin & 15;
        float4 zv = *(const float4*)(zbase + (size_t)c * HW + m4 * 4);
        float e0 = eg[(m4 * 4 + 0) * 257 + c];
        float e1 = eg[(m4 * 4 + 1) * 257 + c];
        float e2 = eg[(m4 * 4 + 2) * 257 + c];
        float e3 = eg[(m4 * 4 + 3) * 257 + c];
        float d0 = e0 - zv.x, d1 = e1 - zv.y, d2 = e2 - zv.z, d3 = e3 - zv.w;
        lsum += d0 * d0 + d1 * d1 + d2 * d2 + d3 * d3;
        *(float4*)(obase + (size_t)c * HW + m4 * 4) = make_float4(e0, e1, e2, e3);
    }

    // ---- block-reduce loss, atomicAdd global ---------------------------------
    #pragma unroll
    for (int off = 16; off > 0; off >>= 1)
        lsum += __shfl_down_sync(0xFFFFFFFFu, lsum, off);
    if ((tid & 31) == 0) wsum[tid >> 5] = lsum;
    __syncthreads();
    if (tid == 0) {
        float t = 0.f;
        #pragma unroll
        for (int w = 0; w < 8; ++w) t += wsum[w];
        if (out_size > nz)
            atomicAdd(&out[nz], t * (1.25f / 16777216.0f));  // (1+BETA)*mean
    }
}

// ---------------------------------------------------------------------------
extern "C" void kernel_launch(void* const* d_in, const int* in_sizes, int n_in,
                              void* d_out, int out_size) {
    const float* z   = (const float*)d_in[0];
    const float* emb = (const float*)d_in[1];
    float* out = (float*)d_out;
    const int nz = in_sizes[0];   // 16777216 z_q elements

    static cudaError_t _attr = cudaFuncSetAttribute(
        vq_main_kernel, cudaFuncAttributeMaxDynamicSharedMemorySize, SMEM_BYTES);
    (void)_attr;

    vq_esq_kernel<<<4, 256>>>(emb, out, out_size, nz);
    vq_main_kernel<<<1024, NTHREADS, SMEM_BYTES>>>(z, emb, out, out_size, nz);
}

// round 11
// speedup vs baseline: 1.3731x; 1.3731x over previous
#include <cuda_runtime.h>
#include <cuda_bf16.h>
#include <cstdint>

// Problem constants
#define CDIM   256
#define HW     1024            // 32*32
#define KCODE  1024
#define MROWS  128             // z rows per CTA
#define KCHUNK 64              // codes per chunk
#define NCHUNK (KCODE / KCHUNK)   // 16
#define NTHREADS 256
#define DELTA  4e-4f           // screen safety window (see analysis)

// smem (dynamic, bf16 elems): A (z_cat) [128][520], B (e_cat chunk) [64][520]
//   k' layout: cols 0..255 = hi, 256..511 = lo (3rd GEMM segment reuses hi)
// overlays after GEMM: et_slow (64x257 f32) on B; eg (256x132 f32) on whole.
#define AB_STRIDE 520                       // 512 + 8 pad (bank-spread)
#define A_BF16    (MROWS * AB_STRIDE)       // 66560
#define B_BF16    (KCHUNK * AB_STRIDE)      // 33280
#define SMEM_BYTES ((A_BF16 + B_BF16) * 2)  // 199680 B

__device__ float g_esq[KCODE];
__device__ __nv_bfloat16 g_ecat[KCODE * 512];   // [k][0:256)=hi, [256:512)=lo

// ---------------------------------------------------------------------------
__device__ __forceinline__ unsigned order_f(float f) {
    unsigned u = __float_as_uint(f);
    return (u & 0x80000000u) ? ~u : (u | 0x80000000u);
}
__device__ __forceinline__ float unorder_f(unsigned u) {
    return __uint_as_float((u & 0x80000000u) ? (u & 0x7FFFFFFFu) : ~u);
}

__device__ __forceinline__ void mma16816(float& c0, float& c1, float& c2, float& c3,
                                         uint32_t a0, uint32_t a1, uint32_t a2,
                                         uint32_t a3, uint32_t b0, uint32_t b1) {
    asm volatile(
        "mma.sync.aligned.m16n8k16.row.col.f32.bf16.bf16.f32 "
        "{%0,%1,%2,%3}, {%4,%5,%6,%7}, {%8,%9}, {%0,%1,%2,%3};"
        : "+f"(c0), "+f"(c1), "+f"(c2), "+f"(c3)
        : "r"(a0), "r"(a1), "r"(a2), "r"(a3), "r"(b0), "r"(b1));
}

// ---------------------------------------------------------------------------
// Prep: e_cat bf16 split; e_sq exact sequential; zero loss slot.
// ---------------------------------------------------------------------------
__global__ void vq_prep_kernel(const float* __restrict__ emb,
                               float* __restrict__ out, int out_size, int nz) {
    int k = blockIdx.x, c = threadIdx.x;
    float e = emb[k * CDIM + c];
    __nv_bfloat16 hi = __float2bfloat16(e);
    float hif = __bfloat162float(hi);
    __nv_bfloat16 lo = __float2bfloat16(e - hif);
    g_ecat[k * 512 + c]       = hi;
    g_ecat[k * 512 + 256 + c] = lo;
    if (c == 0) {
        const float* ep = emb + k * CDIM;
        float s = 0.f;
        #pragma unroll 8
        for (int i = 0; i < CDIM; ++i)
            s = __fadd_rn(s, __fmul_rn(ep[i], ep[i]));
        g_esq[k] = s;
    }
    if (k == 0 && c == 0 && out_size > nz) out[nz] = 0.0f;
}

// ---------------------------------------------------------------------------
// Main: 256 thr, 1 CTA/SM, grid 512 (128 rows each). bf16-split HMMA screen
// (top-2 per row), exact fp32 slow path for ambiguous rows, gather+loss.
// ---------------------------------------------------------------------------
__global__ __launch_bounds__(NTHREADS, 1)
void vq_main_kernel(const float* __restrict__ z,
                    const float* __restrict__ emb,
                    float* __restrict__ out, int out_size, int nz) {
    extern __shared__ __nv_bfloat16 smem_bf[];
    __nv_bfloat16* Asm = smem_bf;               // [row*520 + k']
    __nv_bfloat16* Bsm = smem_bf + A_BF16;      // [code*520 + k']
    float* et_slow = (float*)(smem_bf + A_BF16);      // 64x257 f32 overlay
    float* eg      = (float*)smem_bf;                 // 256x132 f32 overlay

    __shared__ unsigned long long red1[MROWS];
    __shared__ unsigned red2[MROWS];
    __shared__ float zsq_sm[MROWS];
    __shared__ int   winner_sm[MROWS];
    __shared__ unsigned char slow_rows[MROWS];
    __shared__ int slow_cnt;
    __shared__ float zs_slow[4 * CDIM];
    __shared__ float wsum[8];

    const int tid  = threadIdx.x;
    const int w    = tid >> 5;
    const int lane = tid & 31;
    const int g    = lane >> 2;
    const int q    = lane & 3;
    const int b    = blockIdx.x >> 3;
    const int hw0  = (blockIdx.x & 7) * MROWS;

    const float* zbase = z + (size_t)b * CDIM * HW + hw0;

    if (tid < MROWS) { red1[tid] = ~0ull; red2[tid] = 0xFFFFFFFFu; }
    if (tid == 0) slow_cnt = 0;

    // ---- build A (z_cat bf16 split) -----------------------------------------
    #pragma unroll 4
    for (int it = 0; it < 32; ++it) {
        int lin = it * NTHREADS + tid;     // 8192 float4
        int c   = lin >> 5;
        int m4  = lin & 31;
        float4 v = *(const float4*)(zbase + (size_t)c * HW + m4 * 4);
        float zv[4] = {v.x, v.y, v.z, v.w};
        #pragma unroll
        for (int i = 0; i < 4; ++i) {
            int row = m4 * 4 + i;
            __nv_bfloat16 hi = __float2bfloat16(zv[i]);
            float hif = __bfloat162float(hi);
            Asm[row * AB_STRIDE + c]       = hi;
            Asm[row * AB_STRIDE + 256 + c] = __float2bfloat16(zv[i] - hif);
        }
    }

    // ---- z_sq exact per row (sequential fp32 mul+add, ascending c) ----------
    if (tid < MROWS) {
        float s = 0.f;
        #pragma unroll 8
        for (int c = 0; c < CDIM; ++c) {
            float v = zbase[(size_t)c * HW + tid];
            s = __fadd_rn(s, __fmul_rn(v, v));
        }
        zsq_sm[tid] = s;
    }
    __syncthreads();

    // ---- screen state: this thread owns 4 rows ------------------------------
    // warp w: m-tiles 2*(w&3), 2*(w&3)+1 ; n-tiles (w>>2)*4 + {0..3}
    const int mrow0 = 32 * (w & 3);
    const int nbase = (w >> 2) * 32;
    float mn1[4], mn2[4]; int id1[4];
    #pragma unroll
    for (int i = 0; i < 4; ++i) { mn1[i] = 3.4e38f; mn2[i] = 3.4e38f; id1[i] = 0; }

    for (int chunk = 0; chunk < NCHUNK; ++chunk) {
        __syncthreads();   // previous GEMM read Bsm
        // ---- fill B chunk: 64 codes x 512 bf16 (uint4 LDG, uint4 STS) -------
        #pragma unroll 4
        for (int it = 0; it < 16; ++it) {
            int lin = it * NTHREADS + tid;   // 4096 uint4 (8 bf16 each)
            int code = lin >> 6;
            int k8   = (lin & 63) * 8;
            uint4 v = *(const uint4*)&g_ecat[(size_t)(chunk * KCHUNK + code) * 512 + k8];
            *(uint4*)&Bsm[code * AB_STRIDE + k8] = v;
        }
        __syncthreads();

        // ---- GEMM: 3 segments (zh*eh, zh*el, zl*eh), K=256 each -------------
        float acc[2][4][4];
        #pragma unroll
        for (int mt = 0; mt < 2; ++mt)
            #pragma unroll
            for (int nt = 0; nt < 4; ++nt)
                #pragma unroll
                for (int i = 0; i < 4; ++i) acc[mt][nt][i] = 0.f;

        #pragma unroll
        for (int seg = 0; seg < 3; ++seg) {
            const int aoff = (seg == 2) ? 256 : 0;
            const int boff = (seg == 1) ? 256 : 0;
            #pragma unroll 4
            for (int kk = 0; kk < 16; ++kk) {
                int ka = kk * 16 + aoff + q * 2;
                int kb = kk * 16 + boff + q * 2;
                uint32_t a[2][4];
                #pragma unroll
                for (int mt = 0; mt < 2; ++mt) {
                    int r0 = mrow0 + mt * 16 + g;
                    a[mt][0] = *(const uint32_t*)&Asm[r0 * AB_STRIDE + ka];
                    a[mt][1] = *(const uint32_t*)&Asm[(r0 + 8) * AB_STRIDE + ka];
                    a[mt][2] = *(const uint32_t*)&Asm[r0 * AB_STRIDE + ka + 8];
                    a[mt][3] = *(const uint32_t*)&Asm[(r0 + 8) * AB_STRIDE + ka + 8];
                }
                #pragma unroll
                for (int nt = 0; nt < 4; ++nt) {
                    int code0 = nbase + nt * 8 + g;
                    uint32_t b0 = *(const uint32_t*)&Bsm[code0 * AB_STRIDE + kb];
                    uint32_t b1 = *(const uint32_t*)&Bsm[code0 * AB_STRIDE + kb + 8];
                    #pragma unroll
                    for (int mt = 0; mt < 2; ++mt)
                        mma16816(acc[mt][nt][0], acc[mt][nt][1],
                                 acc[mt][nt][2], acc[mt][nt][3],
                                 a[mt][0], a[mt][1], a[mt][2], a[mt][3], b0, b1);
                }
            }
        }

        // ---- fold: screen score s = esq - 2*S, track top-2 per row ----------
        #pragma unroll
        for (int mt = 0; mt < 2; ++mt) {
            #pragma unroll
            for (int half = 0; half < 2; ++half) {
                int rloc = mt * 2 + half;
                #pragma unroll
                for (int nt = 0; nt < 4; ++nt) {
                    int kb0 = chunk * KCHUNK + nbase + nt * 8 + q * 2;
                    #pragma unroll
                    for (int i = 0; i < 2; ++i) {
                        int k = kb0 + i;
                        float S = acc[mt][nt][half * 2 + i];
                        float s = __ldg(&g_esq[k]) - 2.0f * S;
                        if (s < mn1[rloc]) {
                            mn2[rloc] = mn1[rloc]; mn1[rloc] = s; id1[rloc] = k;
                        } else if (s < mn2[rloc]) {
                            mn2[rloc] = s;
                        }
                    }
                }
            }
        }
    }

    // ---- cross-thread top-2 merge -------------------------------------------
    #pragma unroll
    for (int rloc = 0; rloc < 4; ++rloc) {
        int r = mrow0 + (rloc >> 1) * 16 + (rloc & 1) * 8 + g;
        unsigned long long key =
            ((unsigned long long)order_f(mn1[rloc]) << 32) | (unsigned)id1[rloc];
        atomicMin(&red1[r], key);
    }
    __syncthreads();
    #pragma unroll
    for (int rloc = 0; rloc < 4; ++rloc) {
        int r = mrow0 + (rloc >> 1) * 16 + (rloc & 1) * 8 + g;
        unsigned long long key =
            ((unsigned long long)order_f(mn1[rloc]) << 32) | (unsigned)id1[rloc];
        float cand = (key == red1[r]) ? mn2[rloc] : mn1[rloc];
        atomicMin(&red2[r], order_f(cand));
    }
    __syncthreads();

    // ---- winner (fast path) + ambiguity detection ---------------------------
    if (tid < MROWS) {
        winner_sm[tid] = (int)(red1[tid] & 0xFFFFFFFFull);
        float f1 = unorder_f((unsigned)(red1[tid] >> 32));
        float f2 = unorder_f(red2[tid]);
        if (f2 - f1 <= DELTA) {
            int p = atomicAdd(&slow_cnt, 1);
            slow_rows[p] = (unsigned char)tid;
        }
    }
    __syncthreads();

    // ---- slow path: exact fp32 argmin, reference-faithful comparator --------
    int nslow = slow_cnt;
    for (int g0 = 0; g0 < nslow; g0 += 4) {
        int ng = nslow - g0; if (ng > 4) ng = 4;
        #pragma unroll
        for (int gi = 0; gi < 4; ++gi) {
            if (gi < ng) {
                int r = slow_rows[g0 + gi];
                zs_slow[gi * CDIM + tid] = zbase[(size_t)tid * HW + r];
            }
        }
        if (tid < ng) red1[slow_rows[g0 + tid]] = ~0ull;
        __syncthreads();

        for (int chunk = 0; chunk < NCHUNK; ++chunk) {
            // stage 64 emb rows f32, stride 257
            #pragma unroll 4
            for (int it = 0; it < 16; ++it) {
                int lin = it * NTHREADS + tid;   // 4096 float4
                int code = lin >> 6;
                int c4 = (lin & 63) * 4;
                float4 v = *(const float4*)
                    (emb + (size_t)(chunk * KCHUNK + code) * CDIM + c4);
                float* d = et_slow + code * 257 + c4;
                d[0] = v.x; d[1] = v.y; d[2] = v.z; d[3] = v.w;
            }
            __syncthreads();
            int gi = tid >> 6, cidx = tid & 63;
            if (gi < ng) {
                int r = slow_rows[g0 + gi];
                int k = chunk * KCHUNK + cidx;
                const float* zr = zs_slow + gi * CDIM;
                const float* er = et_slow + cidx * 257;
                float s = 0.f;
                #pragma unroll 8
                for (int c = 0; c < CDIM; ++c)
                    s = __fmaf_rn(zr[c], er[c], s);   // exact ascending chain
                float d = __fsub_rn(__fadd_rn(zsq_sm[r], __ldg(&g_esq[k])),
                                    __fmul_rn(2.0f, s));
                unsigned long long key =
                    ((unsigned long long)order_f(d) << 32) | (unsigned)k;
                atomicMin(&red1[r], key);
            }
            __syncthreads();
        }
        if (tid < ng) {
            int r = slow_rows[g0 + tid];
            winner_sm[r] = (int)(red1[r] & 0xFFFFFFFFull);
        }
        __syncthreads();
    }
    __syncthreads();

    // ---- gather: eg[c*132 + m] = emb[winner[m]][c] --------------------------
    #pragma unroll 4
    for (int m = 0; m < MROWS; ++m) {
        eg[tid * 132 + m] = emb[(size_t)winner_sm[m] * CDIM + tid];
    }
    __syncthreads();

    // ---- write z_q (float4) + loss partial ----------------------------------
    float lsum = 0.f;
    float* obase = out + (size_t)b * CDIM * HW + hw0;
    #pragma unroll 4
    for (int it = 0; it < 32; ++it) {
        int lin = it * NTHREADS + tid;   // 8192 float4
        int c   = lin >> 5;
        int m4  = lin & 31;
        float4 ev = *(const float4*)&eg[c * 132 + m4 * 4];
        float4 zv = *(const float4*)(zbase + (size_t)c * HW + m4 * 4);
        float d0 = ev.x - zv.x, d1 = ev.y - zv.y;
        float d2 = ev.z - zv.z, d3 = ev.w - zv.w;
        lsum += d0 * d0 + d1 * d1 + d2 * d2 + d3 * d3;
        *(float4*)(obase + (size_t)c * HW + m4 * 4) = ev;
    }

    #pragma unroll
    for (int off = 16; off > 0; off >>= 1)
        lsum += __shfl_down_sync(0xFFFFFFFFu, lsum, off);
    if (lane == 0) wsum[w] = lsum;
    __syncthreads();
    if (tid == 0) {
        float t = 0.f;
        #pragma unroll
        for (int i = 0; i < 8; ++i) t += wsum[i];
        if (out_size > nz)
            atomicAdd(&out[nz], t * (1.25f / 16777216.0f));  // (1+BETA)*mean
    }
}

// ---------------------------------------------------------------------------
extern "C" void kernel_launch(void* const* d_in, const int* in_sizes, int n_in,
                              void* d_out, int out_size) {
    const float* z   = (const float*)d_in[0];
    const float* emb = (const float*)d_in[1];
    float* out = (float*)d_out;
    const int nz = in_sizes[0];   // 16777216 z_q elements

    static cudaError_t _attr = cudaFuncSetAttribute(
        vq_main_kernel, cudaFuncAttributeMaxDynamicSharedMemorySize, SMEM_BYTES);
    (void)_attr;

    vq_prep_kernel<<<KCODE, 256>>>(emb, out, out_size, nz);
    vq_main_kernel<<<512, NTHREADS, SMEM_BYTES>>>(z, emb, out, out_size, nz);
}

// round 13
// speedup vs baseline: 1.4265x; 1.0389x over previous
#include <cuda_runtime.h>
#include <cuda_bf16.h>
#include <cstdint>

// Problem constants
#define CDIM   256
#define HW     1024            // 32*32
#define KCODE  1024
#define MROWS  128             // z rows per CTA
#define KCHUNK 64              // codes per chunk
#define NCHUNK (KCODE / KCHUNK)   // 16
#define NTHREADS 256
#define DELTA  4e-4f           // screen safety window

// smem (dynamic, bf16 elems): A (z_cat) [128][520], B (e_cat chunk) [64][520]
//   k' layout: cols 0..255 = hi, 256..511 = lo
// overlays after GEMM: et_slow (64x257 f32) on B; eg (256x132 f32) on whole.
#define AB_STRIDE 520                       // 512 + 8 pad (bank-spread)
#define A_BF16    (MROWS * AB_STRIDE)       // 66560
#define B_BF16    (KCHUNK * AB_STRIDE)      // 33280
#define SMEM_BYTES ((A_BF16 + B_BF16) * 2)  // 199680 B

__device__ float g_esq[KCODE];
__device__ __nv_bfloat16 g_ecat[KCODE * 512];   // [k][0:256)=hi, [256:512)=lo

// ---------------------------------------------------------------------------
__device__ __forceinline__ unsigned order_f(float f) {
    unsigned u = __float_as_uint(f);
    return (u & 0x80000000u) ? ~u : (u | 0x80000000u);
}
__device__ __forceinline__ float unorder_f(unsigned u) {
    return __uint_as_float((u & 0x80000000u) ? (u & 0x7FFFFFFFu) : ~u);
}
__device__ __forceinline__ uint32_t smem_u32(const void* p) {
    return (uint32_t)__cvta_generic_to_shared(p);
}
__device__ __forceinline__ void ldsm_x4(uint32_t& r0, uint32_t& r1,
                                        uint32_t& r2, uint32_t& r3, uint32_t a) {
    asm volatile("ldmatrix.sync.aligned.m8n8.x4.shared.b16 {%0,%1,%2,%3}, [%4];"
                 : "=r"(r0), "=r"(r1), "=r"(r2), "=r"(r3) : "r"(a));
}
__device__ __forceinline__ void mma16816(float& c0, float& c1, float& c2, float& c3,
                                         uint32_t a0, uint32_t a1, uint32_t a2,
                                         uint32_t a3, uint32_t b0, uint32_t b1) {
    asm volatile(
        "mma.sync.aligned.m16n8k16.row.col.f32.bf16.bf16.f32 "
        "{%0,%1,%2,%3}, {%4,%5,%6,%7}, {%8,%9}, {%0,%1,%2,%3};"
        : "+f"(c0), "+f"(c1), "+f"(c2), "+f"(c3)
        : "r"(a0), "r"(a1), "r"(a2), "r"(a3), "r"(b0), "r"(b1));
}

// ---------------------------------------------------------------------------
// Prep: e_cat bf16 split; e_sq exact sequential; zero loss slot.
// ---------------------------------------------------------------------------
__global__ void vq_prep_kernel(const float* __restrict__ emb,
                               float* __restrict__ out, int out_size, int nz) {
    int k = blockIdx.x, c = threadIdx.x;
    float e = emb[k * CDIM + c];
    __nv_bfloat16 hi = __float2bfloat16(e);
    float hif = __bfloat162float(hi);
    __nv_bfloat16 lo = __float2bfloat16(e - hif);
    g_ecat[k * 512 + c]       = hi;
    g_ecat[k * 512 + 256 + c] = lo;
    if (c == 0) {
        const float* ep = emb + k * CDIM;
        float s = 0.f;
        #pragma unroll 8
        for (int i = 0; i < CDIM; ++i)
            s = __fadd_rn(s, __fmul_rn(ep[i], ep[i]));
        g_esq[k] = s;
    }
    if (k == 0 && c == 0 && out_size > nz) out[nz] = 0.0f;
}

// ---------------------------------------------------------------------------
// Main: 256 thr, 1 CTA/SM, grid 512 (128 rows each). bf16-split HMMA screen
// with LDSM fragment loads, exact fp32 slow path, gather+loss.
// ---------------------------------------------------------------------------
__global__ __launch_bounds__(NTHREADS, 1)
void vq_main_kernel(const float* __restrict__ z,
                    const float* __restrict__ emb,
                    float* __restrict__ out, int out_size, int nz) {
    extern __shared__ __nv_bfloat16 smem_bf[];
    __nv_bfloat16* Asm = smem_bf;               // [row*520 + k']
    __nv_bfloat16* Bsm = smem_bf + A_BF16;      // [code*520 + k']
    float* et_slow = (float*)(smem_bf + A_BF16);      // 64x257 f32 overlay
    float* eg      = (float*)smem_bf;                 // 256x132 f32 overlay

    __shared__ unsigned long long red1[MROWS];
    __shared__ unsigned red2[MROWS];
    __shared__ float zsq_sm[MROWS];
    __shared__ int   winner_sm[MROWS];
    __shared__ unsigned char slow_rows[MROWS];
    __shared__ int slow_cnt;
    __shared__ float zs_slow[4 * CDIM];
    __shared__ float wsum[8];

    const int tid  = threadIdx.x;
    const int w    = tid >> 5;
    const int lane = tid & 31;
    const int g    = lane >> 2;
    const int q    = lane & 3;
    const int b    = blockIdx.x >> 3;
    const int hw0  = (blockIdx.x & 7) * MROWS;

    const float* zbase = z + (size_t)b * CDIM * HW + hw0;

    if (tid < MROWS) { red1[tid] = ~0ull; red2[tid] = 0xFFFFFFFFu; }
    if (tid == 0) slow_cnt = 0;

    // ---- build A (z_cat bf16 split) -----------------------------------------
    #pragma unroll 4
    for (int it = 0; it < 32; ++it) {
        int lin = it * NTHREADS + tid;     // 8192 float4
        int c   = lin >> 5;
        int m4  = lin & 31;
        float4 v = *(const float4*)(zbase + (size_t)c * HW + m4 * 4);
        float zv[4] = {v.x, v.y, v.z, v.w};
        #pragma unroll
        for (int i = 0; i < 4; ++i) {
            int row = m4 * 4 + i;
            __nv_bfloat16 hi = __float2bfloat16(zv[i]);
            float hif = __bfloat162float(hi);
            Asm[row * AB_STRIDE + c]       = hi;
            Asm[row * AB_STRIDE + 256 + c] = __float2bfloat16(zv[i] - hif);
        }
    }

    // ---- z_sq exact per row (sequential fp32 mul+add, ascending c) ----------
    if (tid < MROWS) {
        float s = 0.f;
        #pragma unroll 8
        for (int c = 0; c < CDIM; ++c) {
            float v = zbase[(size_t)c * HW + tid];
            s = __fadd_rn(s, __fmul_rn(v, v));
        }
        zsq_sm[tid] = s;
    }
    __syncthreads();

    // ---- screen state: warp w -> m-rows 32*(w&3).., codes (w>>2)*32.. -------
    const int mrow0 = 32 * (w & 3);
    const int nbase = (w >> 2) * 32;
    float mn1[4], mn2[4]; int id1[4];
    #pragma unroll
    for (int i = 0; i < 4; ++i) { mn1[i] = 3.4e38f; mn2[i] = 3.4e38f; id1[i] = 0; }

    // ---- per-lane LDSM base addresses (bf16-elem offsets * 2 bytes) ---------
    // A mats: m0k0 / m8k0 / m0k8 / m8k8
    uint32_t aAddr[2];
    #pragma unroll
    for (int mt = 0; mt < 2; ++mt) {
        int lrow = mrow0 + mt * 16 + (lane & 7) + ((lane >> 3) & 1) * 8;
        int lkof = ((lane >> 4) & 1) * 8;
        aAddr[mt] = smem_u32(Asm) + (uint32_t)(lrow * AB_STRIDE + lkof) * 2;
    }
    // B mats: (nt,k0) / (nt,k8) / (nt+1,k0) / (nt+1,k8)
    uint32_t bAddr[2];
    #pragma unroll
    for (int ntp = 0; ntp < 2; ++ntp) {
        int lcode = nbase + (ntp * 2 + ((lane >> 4) & 1)) * 8 + (lane & 7);
        int lkof  = ((lane >> 3) & 1) * 8;
        bAddr[ntp] = smem_u32(Bsm) + (uint32_t)(lcode * AB_STRIDE + lkof) * 2;
    }

    for (int chunk = 0; chunk < NCHUNK; ++chunk) {
        __syncthreads();   // previous GEMM read Bsm
        // ---- fill B chunk: 64 codes x 512 bf16 (uint4 LDG, uint4 STS) -------
        #pragma unroll 4
        for (int it = 0; it < 16; ++it) {
            int lin = it * NTHREADS + tid;   // 4096 uint4 (8 bf16 each)
            int code = lin >> 6;
            int k8   = (lin & 63) * 8;
            uint4 v = *(const uint4*)&g_ecat[(size_t)(chunk * KCHUNK + code) * 512 + k8];
            *(uint4*)&Bsm[code * AB_STRIDE + k8] = v;
        }
        __syncthreads();

        // ---- GEMM: 3 segments (zh*eh, zh*el, zl*eh), K=256 each -------------
        float acc[2][4][4];
        #pragma unroll
        for (int mt = 0; mt < 2; ++mt)
            #pragma unroll
            for (int nt = 0; nt < 4; ++nt)
                #pragma unroll
                for (int i = 0; i < 4; ++i) acc[mt][nt][i] = 0.f;

        #pragma unroll
        for (int seg = 0; seg < 3; ++seg) {
            const uint32_t aoff = ((seg == 2) ? 256u : 0u) * 2;
            const uint32_t boff = ((seg == 1) ? 256u : 0u) * 2;
            #pragma unroll 4
            for (int kk = 0; kk < 16; ++kk) {
                uint32_t kbyte = (uint32_t)(kk * 16) * 2;
                uint32_t a[2][4], bb[2][4];
                ldsm_x4(a[0][0], a[0][1], a[0][2], a[0][3], aAddr[0] + aoff + kbyte);
                ldsm_x4(a[1][0], a[1][1], a[1][2], a[1][3], aAddr[1] + aoff + kbyte);
                ldsm_x4(bb[0][0], bb[0][1], bb[0][2], bb[0][3], bAddr[0] + boff + kbyte);
                ldsm_x4(bb[1][0], bb[1][1], bb[1][2], bb[1][3], bAddr[1] + boff + kbyte);
                #pragma unroll
                for (int nt = 0; nt < 4; ++nt) {
                    uint32_t b0 = bb[nt >> 1][(nt & 1) * 2];
                    uint32_t b1 = bb[nt >> 1][(nt & 1) * 2 + 1];
                    #pragma unroll
                    for (int mt = 0; mt < 2; ++mt)
                        mma16816(acc[mt][nt][0], acc[mt][nt][1],
                                 acc[mt][nt][2], acc[mt][nt][3],
                                 a[mt][0], a[mt][1], a[mt][2], a[mt][3], b0, b1);
                }
            }
        }

        // ---- fold: screen score s = esq - 2*S, track top-2 per row ----------
        #pragma unroll
        for (int mt = 0; mt < 2; ++mt) {
            #pragma unroll
            for (int half = 0; half < 2; ++half) {
                int rloc = mt * 2 + half;
                #pragma unroll
                for (int nt = 0; nt < 4; ++nt) {
                    int kb0 = chunk * KCHUNK + nbase + nt * 8 + q * 2;
                    #pragma unroll
                    for (int i = 0; i < 2; ++i) {
                        int k = kb0 + i;
                        float S = acc[mt][nt][half * 2 + i];
                        float s = __ldg(&g_esq[k]) - 2.0f * S;
                        if (s < mn1[rloc]) {
                            mn2[rloc] = mn1[rloc]; mn1[rloc] = s; id1[rloc] = k;
                        } else if (s < mn2[rloc]) {
                            mn2[rloc] = s;
                        }
                    }
                }
            }
        }
    }

    // ---- cross-thread top-2 merge -------------------------------------------
    #pragma unroll
    for (int rloc = 0; rloc < 4; ++rloc) {
        int r = mrow0 + (rloc >> 1) * 16 + (rloc & 1) * 8 + g;
        unsigned long long key =
            ((unsigned long long)order_f(mn1[rloc]) << 32) | (unsigned)id1[rloc];
        atomicMin(&red1[r], key);
    }
    __syncthreads();
    #pragma unroll
    for (int rloc = 0; rloc < 4; ++rloc) {
        int r = mrow0 + (rloc >> 1) * 16 + (rloc & 1) * 8 + g;
        unsigned long long key =
            ((unsigned long long)order_f(mn1[rloc]) << 32) | (unsigned)id1[rloc];
        float cand = (key == red1[r]) ? mn2[rloc] : mn1[rloc];
        atomicMin(&red2[r], order_f(cand));
    }
    __syncthreads();

    // ---- winner (fast path) + ambiguity detection ---------------------------
    if (tid < MROWS) {
        winner_sm[tid] = (int)(red1[tid] & 0xFFFFFFFFull);
        float f1 = unorder_f((unsigned)(red1[tid] >> 32));
        float f2 = unorder_f(red2[tid]);
        if (f2 - f1 <= DELTA) {
            int p = atomicAdd(&slow_cnt, 1);
            slow_rows[p] = (unsigned char)tid;
        }
    }
    __syncthreads();

    // ---- slow path: exact fp32 argmin, reference-faithful comparator --------
    int nslow = slow_cnt;
    for (int g0 = 0; g0 < nslow; g0 += 4) {
        int ng = nslow - g0; if (ng > 4) ng = 4;
        #pragma unroll
        for (int gi = 0; gi < 4; ++gi) {
            if (gi < ng) {
                int r = slow_rows[g0 + gi];
                zs_slow[gi * CDIM + tid] = zbase[(size_t)tid * HW + r];
            }
        }
        if (tid < ng) red1[slow_rows[g0 + tid]] = ~0ull;
        __syncthreads();

        for (int chunk = 0; chunk < NCHUNK; ++chunk) {
            #pragma unroll 4
            for (int it = 0; it < 16; ++it) {
                int lin = it * NTHREADS + tid;   // 4096 float4
                int code = lin >> 6;
                int c4 = (lin & 63) * 4;
                float4 v = *(const float4*)
                    (emb + (size_t)(chunk * KCHUNK + code) * CDIM + c4);
                float* d = et_slow + code * 257 + c4;
                d[0] = v.x; d[1] = v.y; d[2] = v.z; d[3] = v.w;
            }
            __syncthreads();
            int gi = tid >> 6, cidx = tid & 63;
            if (gi < ng) {
                int r = slow_rows[g0 + gi];
                int k = chunk * KCHUNK + cidx;
                const float* zr = zs_slow + gi * CDIM;
                const float* er = et_slow + cidx * 257;
                float s = 0.f;
                #pragma unroll 8
                for (int c = 0; c < CDIM; ++c)
                    s = __fmaf_rn(zr[c], er[c], s);   // exact ascending chain
                float d = __fsub_rn(__fadd_rn(zsq_sm[r], __ldg(&g_esq[k])),
                                    __fmul_rn(2.0f, s));
                unsigned long long key =
                    ((unsigned long long)order_f(d) << 32) | (unsigned)k;
                atomicMin(&red1[r], key);
            }
            __syncthreads();
        }
        if (tid < ng) {
            int r = slow_rows[g0 + tid];
            winner_sm[r] = (int)(red1[r] & 0xFFFFFFFFull);
        }
        __syncthreads();
    }
    __syncthreads();

    // ---- gather: eg[c*132 + m] = emb[winner[m]][c] --------------------------
    #pragma unroll 4
    for (int m = 0; m < MROWS; ++m) {
        eg[tid * 132 + m] = emb[(size_t)winner_sm[m] * CDIM + tid];
    }
    __syncthreads();

    // ---- write z_q (float4) + loss partial ----------------------------------
    float lsum = 0.f;
    float* obase = out + (size_t)b * CDIM * HW + hw0;
    #pragma unroll 4
    for (int it = 0; it < 32; ++it) {
        int lin = it * NTHREADS + tid;   // 8192 float4
        int c   = lin >> 5;
        int m4  = lin & 31;
        float4 ev = *(const float4*)&eg[c * 132 + m4 * 4];
        float4 zv = *(const float4*)(zbase + (size_t)c * HW + m4 * 4);
        float d0 = ev.x - zv.x, d1 = ev.y - zv.y;
        float d2 = ev.z - zv.z, d3 = ev.w - zv.w;
        lsum += d0 * d0 + d1 * d1 + d2 * d2 + d3 * d3;
        *(float4*)(obase + (size_t)c * HW + m4 * 4) = ev;
    }

    #pragma unroll
    for (int off = 16; off > 0; off >>= 1)
        lsum += __shfl_down_sync(0xFFFFFFFFu, lsum, off);
    if (lane == 0) wsum[w] = lsum;
    __syncthreads();
    if (tid == 0) {
        float t = 0.f;
        #pragma unroll
        for (int i = 0; i < 8; ++i) t += wsum[i];
        if (out_size > nz)
            atomicAdd(&out[nz], t * (1.25f / 16777216.0f));  // (1+BETA)*mean
    }
}

// ---------------------------------------------------------------------------
extern "C" void kernel_launch(void* const* d_in, const int* in_sizes, int n_in,
                              void* d_out, int out_size) {
    const float* z   = (const float*)d_in[0];
    const float* emb = (const float*)d_in[1];
    float* out = (float*)d_out;
    const int nz = in_sizes[0];   // 16777216 z_q elements

    static cudaError_t _attr = cudaFuncSetAttribute(
        vq_main_kernel, cudaFuncAttributeMaxDynamicSharedMemorySize, SMEM_BYTES);
    (void)_attr;

    vq_prep_kernel<<<KCODE, 256>>>(emb, out, out_size, nz);
    vq_main_kernel<<<512, NTHREADS, SMEM_BYTES>>>(z, emb, out, out_size, nz);
}